// round 14
// baseline (speedup 1.0000x reference)
#include <cuda_runtime.h>
#include <cuda_fp16.h>
#include <cstdint>
#include <cstddef>

#define NR 8192
#define MR 8192
#define HD 512

// ---------------- scratch (device globals: allowed) ----------------
__device__ __align__(128) __half g_fh[(size_t)NR * HD], g_fl[(size_t)NR * HD];
__device__ __align__(128) __half g_mh[(size_t)MR * HD], g_ml[(size_t)MR * HD];
__device__ __align__(128) __half g_t1h[HD * HD], g_t1l[HD * HD];
__device__ __align__(128) float  g_c[HD];
__device__ __align__(128) __half g_qh[(size_t)NR * HD], g_ql[(size_t)NR * HD];
__device__ __align__(128) __half g_mth[(size_t)HD * MR];
__device__ __align__(128) float  g_s[(size_t)NR * MR];
__device__ __align__(128) __half g_ph[(size_t)NR * MR];

// ---------------- helpers ----------------
__device__ __forceinline__ uint32_t smem_u32(const void* p) {
    uint32_t a;
    asm("{ .reg .u64 t; cvta.to.shared.u64 t, %1; cvt.u32.u64 %0, t; }" : "=r"(a) : "l"(p));
    return a;
}
__device__ __forceinline__ void cp16(uint32_t dst, const void* src) {
    asm volatile("cp.async.cg.shared.global [%0], [%1], 16;" :: "r"(dst), "l"(src));
}
__device__ __forceinline__ void ldsm4(uint32_t* r, uint32_t addr) {
    asm volatile("ldmatrix.sync.aligned.m8n8.x4.shared.b16 {%0,%1,%2,%3}, [%4];"
        : "=r"(r[0]), "=r"(r[1]), "=r"(r[2]), "=r"(r[3]) : "r"(addr));
}
__device__ __forceinline__ void mma16816(float* c, const uint32_t* a, const uint32_t* b) {
    asm volatile("mma.sync.aligned.m16n8k16.row.col.f32.f16.f16.f32 "
        "{%0,%1,%2,%3}, {%4,%5,%6,%7}, {%8,%9}, {%0,%1,%2,%3};"
        : "+f"(c[0]), "+f"(c[1]), "+f"(c[2]), "+f"(c[3])
        : "r"(a[0]), "r"(a[1]), "r"(a[2]), "r"(a[3]), "r"(b[0]), "r"(b[1]));
}
// fp16-accumulate MMA (double-rate on the legacy tensor path)
__device__ __forceinline__ void mma16816h(uint32_t* c, const uint32_t* a, const uint32_t* b) {
    asm volatile("mma.sync.aligned.m16n8k16.row.col.f16.f16.f16.f16 "
        "{%0,%1}, {%2,%3,%4,%5}, {%6,%7}, {%0,%1};"
        : "+r"(c[0]), "+r"(c[1])
        : "r"(a[0]), "r"(a[1]), "r"(a[2]), "r"(a[3]), "r"(b[0]), "r"(b[1]));
}
__device__ __forceinline__ void split1(float v, __half& h, __half& l) {
    h = __float2half_rn(v);
    l = __float2half_rn(v - __half2float(h));
}
__device__ __forceinline__ uint32_t pack2(__half a, __half b) {
    __half2 t = __halves2half2(a, b);
    return *(uint32_t*)&t;
}

// pitch: 32 halfs padded to 40 (80B) -> conflict-free ldmatrix
#define PITCH_B 80
#define MAT_B   (128 * PITCH_B)   // 10240 B per matrix tile

// ---------------- combined split: features AND memory in one launch ----------------
__global__ __launch_bounds__(256)
void split_fm_kernel(const float* __restrict__ f, const float* __restrict__ m,
                     __half* __restrict__ fh, __half* __restrict__ fl,
                     __half* __restrict__ mh, __half* __restrict__ ml, size_t n4)
{
    size_t half_blocks = gridDim.x >> 1;
    const float* s; __half *dh, *dl;
    size_t i;
    if (blockIdx.x < half_blocks) {
        s = f; dh = fh; dl = fl;
        i = (size_t)blockIdx.x * blockDim.x + threadIdx.x;
    } else {
        s = m; dh = mh; dl = ml;
        i = (size_t)(blockIdx.x - half_blocks) * blockDim.x + threadIdx.x;
    }
    if (i >= n4) return;
    float4 v = ((const float4*)s)[i];
    __half hx, lx, hy, ly, hz, lz, hw, lw;
    split1(v.x, hx, lx); split1(v.y, hy, ly);
    split1(v.z, hz, lz); split1(v.w, hw, lw);
    ((uint2*)dh)[i] = make_uint2(pack2(hx, hy), pack2(hz, hw));
    ((uint2*)dl)[i] = make_uint2(pack2(lx, ly), pack2(lz, lw));
}

// ---------------- T1 = Wk^T @ Wq (split-fp16) + c = bq @ Wk (fused) ----------------
__global__ __launch_bounds__(256)
void wprod_cvec_kernel(const float* __restrict__ Wk, const float* __restrict__ Wq,
                       const float* __restrict__ bq,
                       __half* __restrict__ Th, __half* __restrict__ Tl,
                       float* __restrict__ c)
{
    __shared__ float Ks[16][17], Qs[16][17];
    const int i0 = blockIdx.x * 16;
    const int j0 = blockIdx.y * 16;
    const int tx = threadIdx.x & 15;
    const int ty = threadIdx.x >> 4;
    float acc = 0.f;
    for (int t0 = 0; t0 < HD; t0 += 16) {
        Ks[ty][tx] = Wk[(t0 + ty) * HD + i0 + tx];
        Qs[ty][tx] = Wq[(t0 + ty) * HD + j0 + tx];
        __syncthreads();
#pragma unroll
        for (int t = 0; t < 16; ++t)
            acc = fmaf(Ks[t][ty], Qs[t][tx], acc);
        __syncthreads();
    }
    __half h, l; split1(acc, h, l);
    Th[(size_t)(i0 + ty) * HD + j0 + tx] = h;
    Tl[(size_t)(i0 + ty) * HD + j0 + tx] = l;

    if (blockIdx.y == 0) {
        __shared__ float cred[16][17];
        float a = 0.f;
#pragma unroll 4
        for (int t = tx * 32; t < tx * 32 + 32; ++t)
            a = fmaf(bq[t], Wk[t * HD + i0 + ty], a);
        cred[ty][tx] = a;
        __syncthreads();
        if (tx == 0) {
            float s2 = 0.f;
#pragma unroll
            for (int u = 0; u < 16; ++u) s2 += cred[ty][u];
            c[i0 + ty] = s2;
        }
    }
}

// ---------------- mem [MR][HD] fp32 -> memT [HD][MR] fp16 (hi only) ----------------
__global__ __launch_bounds__(256)
void transpose_h(const float* __restrict__ src, __half* __restrict__ dh)
{
    __shared__ float t[32][33];
    const int j0 = blockIdx.x * 32;
    const int h0 = blockIdx.y * 32;
    const int tx = threadIdx.x & 31;
    const int ty = threadIdx.x >> 5;
#pragma unroll
    for (int i = 0; i < 4; ++i)
        t[ty + i * 8][tx] = src[(size_t)(j0 + ty + i * 8) * HD + h0 + tx];
    __syncthreads();
#pragma unroll
    for (int i = 0; i < 4; ++i) {
        size_t o = (size_t)(h0 + ty + i * 8) * MR + j0 + tx;
        dh[o] = __float2half_rn(t[tx][ty + i * 8]);
    }
}

// ---------------------------------------------------------------------------
// NT GEMM via mma.sync. FAT-WARP: CTA 128x128, 128 thr, warps 2x2, tile 64x64.
// NPASS==3: D = Ah*Bh (fp32 acc) + [Ah*Bl + Al*Bh] (fp16 acc, TRANSIENT per
//           ph-group -> folded into fp32 each ph; 32 regs, no spills).
// NPASS==1: D = Ah*Bh (fp32 acc)
// K-chunk 32, NSTG-stage cp.async pipeline, 2 CTAs/SM.
// EPI: 0 = +bias[n], split fp16 out; 1 = fp32 out; 2 = 0.5*F + 0.5*acc (F=biasF)
// ---------------------------------------------------------------------------
template <int EPI, int NPASS, int NSTG>
__global__ __launch_bounds__(128, 2)
void mma_gemm(const __half* __restrict__ Ah, const __half* __restrict__ Al,
              const __half* __restrict__ Bh, const __half* __restrict__ Bl,
              const float* __restrict__ biasF,
              float* __restrict__ outf,
              __half* __restrict__ outh, __half* __restrict__ outl,
              int M, int N, int K)
{
    constexpr int NMAT = (NPASS == 3) ? 4 : 2;
    constexpr uint32_t STAGE = NMAT * MAT_B;

    extern __shared__ char smem[];
    const uint32_t sbase = smem_u32(smem);
    const int tid = threadIdx.x;
    const int wid = tid >> 5;
    const int lane = tid & 31;
    const int bm = blockIdx.y * 128;
    const int bn = blockIdx.x * 128;
    const int wm = (wid & 1) * 64;
    const int wn = (wid >> 1) * 64;

    const int NC = K >> 5;

    const int ldr = tid >> 2;
    const int ldc = (tid & 3) * 16;

    auto loadc = [&](int c) {
        const uint32_t sb = sbase + (uint32_t)(c % NSTG) * STAGE;
        const int k0 = c << 5;
        const __half* pa = Ah + (size_t)(bm + ldr) * K + k0 + ldc / 2;
        const __half* pb = Bh + (size_t)(bn + ldr) * K + k0 + ldc / 2;
#pragma unroll
        for (int i = 0; i < 4; ++i) {
            cp16(sb + (ldr + i * 32) * PITCH_B + ldc,         pa + (size_t)(i * 32) * K);
            cp16(sb + MAT_B + (ldr + i * 32) * PITCH_B + ldc, pb + (size_t)(i * 32) * K);
        }
        if (NPASS == 3) {
            const __half* pc = Bl + (size_t)(bn + ldr) * K + k0 + ldc / 2;
            const __half* pd = Al + (size_t)(bm + ldr) * K + k0 + ldc / 2;
#pragma unroll
            for (int i = 0; i < 4; ++i) {
                cp16(sb + 2 * MAT_B + (ldr + i * 32) * PITCH_B + ldc, pc + (size_t)(i * 32) * K);
                cp16(sb + 3 * MAT_B + (ldr + i * 32) * PITCH_B + ldc, pd + (size_t)(i * 32) * K);
            }
        }
    };

    float acc[4][8][4];
#pragma unroll
    for (int mg = 0; mg < 4; ++mg)
#pragma unroll
        for (int ng = 0; ng < 8; ++ng)
#pragma unroll
            for (int j = 0; j < 4; ++j) acc[mg][ng][j] = 0.f;

    const uint32_t aRow = (lane & 15);
    const uint32_t aChk = (lane >> 4);
    const uint32_t bRow = ((lane >> 4) & 1) * 8 + (lane & 7);
    const uint32_t bChk = (lane >> 3) & 1;

    auto compute = [&](int c) {
        const uint32_t st = sbase + (uint32_t)(c % NSTG) * STAGE;
#pragma unroll
        for (int ks = 0; ks < 2; ++ks) {
            uint32_t ah[4][4], al[4][4];
#pragma unroll
            for (int mg = 0; mg < 4; ++mg) {
                uint32_t off = (wm + mg * 16 + aRow) * PITCH_B + aChk * 16 + ks * 32;
                ldsm4(ah[mg], st + off);
                if (NPASS == 3) ldsm4(al[mg], st + 3 * MAT_B + off);
            }
#pragma unroll
            for (int ph = 0; ph < 2; ++ph) {
                uint32_t bh[2][4], bl[2][4];
#pragma unroll
                for (int p2 = 0; p2 < 2; ++p2) {
                    uint32_t off = (wn + (ph * 2 + p2) * 16 + bRow) * PITCH_B + bChk * 16 + ks * 32;
                    ldsm4(bh[p2], st + MAT_B + off);
                    if (NPASS == 3) ldsm4(bl[p2], st + 2 * MAT_B + off);
                }
                // pass 1: Ah*Bh -> fp32 acc (16 MMAs)
#pragma unroll
                for (int p2 = 0; p2 < 2; ++p2)
#pragma unroll
                    for (int mg = 0; mg < 4; ++mg) {
                        const int ng = 2 * (ph * 2 + p2);
                        mma16816(acc[mg][ng + 0], ah[mg], bh[p2] + 0);
                        mma16816(acc[mg][ng + 1], ah[mg], bh[p2] + 2);
                    }
                if (NPASS == 3) {
                    // cross terms -> transient fp16 acc (32 regs), double rate
                    uint32_t ax[4][4][2];
#pragma unroll
                    for (int mg = 0; mg < 4; ++mg)
#pragma unroll
                        for (int q = 0; q < 4; ++q) {
                            ax[mg][q][0] = 0u; ax[mg][q][1] = 0u;
                        }
                    // pass 2: Ah*Bl
#pragma unroll
                    for (int p2 = 0; p2 < 2; ++p2)
#pragma unroll
                        for (int mg = 0; mg < 4; ++mg) {
                            mma16816h(ax[mg][p2 * 2 + 0], ah[mg], bl[p2] + 0);
                            mma16816h(ax[mg][p2 * 2 + 1], ah[mg], bl[p2] + 2);
                        }
                    // pass 3: Al*Bh
#pragma unroll
                    for (int p2 = 0; p2 < 2; ++p2)
#pragma unroll
                        for (int mg = 0; mg < 4; ++mg) {
                            mma16816h(ax[mg][p2 * 2 + 0], al[mg], bh[p2] + 0);
                            mma16816h(ax[mg][p2 * 2 + 1], al[mg], bh[p2] + 2);
                        }
                    // fold into fp32 (FMA pipe; overlaps next tensor work)
#pragma unroll
                    for (int mg = 0; mg < 4; ++mg)
#pragma unroll
                        for (int q = 0; q < 4; ++q) {
                            const int ng = ph * 4 + q;   // q = p2*2 + half
                            __half2 h0 = *(__half2*)&ax[mg][q][0];
                            __half2 h1 = *(__half2*)&ax[mg][q][1];
                            acc[mg][ng][0] += __low2float(h0);
                            acc[mg][ng][1] += __high2float(h0);
                            acc[mg][ng][2] += __low2float(h1);
                            acc[mg][ng][3] += __high2float(h1);
                        }
                }
            }
        }
    };

    // pipeline: wait(chunk c) -> sync -> prefetch(c+NSTG-1) -> compute(c)
#pragma unroll 1
    for (int c = 0; c < NSTG - 1 && c < NC; ++c) {
        loadc(c);
        asm volatile("cp.async.commit_group;" ::: "memory");
    }
#pragma unroll 1
    for (int c = 0; c < NC; ++c) {
        if (NSTG >= 4 && c + 2 < NC)
            asm volatile("cp.async.wait_group 2;" ::: "memory");
        else if (NSTG >= 3 && c + 1 < NC)
            asm volatile("cp.async.wait_group 1;" ::: "memory");
        else
            asm volatile("cp.async.wait_group 0;" ::: "memory");
        __syncthreads();
        if (c + NSTG - 1 < NC) {
            loadc(c + NSTG - 1);
            asm volatile("cp.async.commit_group;" ::: "memory");
        }
        compute(c);
    }

    // ---------------- epilogue ----------------
#pragma unroll
    for (int mg = 0; mg < 4; ++mg) {
        const int r0 = bm + wm + mg * 16 + (lane >> 2);
#pragma unroll
        for (int ng = 0; ng < 8; ++ng) {
            const int cc = bn + wn + ng * 8 + (lane & 3) * 2;
            const float* a = acc[mg][ng];
            if (EPI == 0) {
                float b0 = biasF[cc], b1 = biasF[cc + 1];
                float v0 = a[0] + b0, v1 = a[1] + b1;
                float v2 = a[2] + b0, v3 = a[3] + b1;
                __half h0, l0, h1, l1, h2, l2, h3, l3;
                split1(v0, h0, l0); split1(v1, h1, l1);
                split1(v2, h2, l2); split1(v3, h3, l3);
                *(uint32_t*)(outh + (size_t)r0 * N + cc)       = pack2(h0, h1);
                *(uint32_t*)(outl + (size_t)r0 * N + cc)       = pack2(l0, l1);
                *(uint32_t*)(outh + (size_t)(r0 + 8) * N + cc) = pack2(h2, h3);
                *(uint32_t*)(outl + (size_t)(r0 + 8) * N + cc) = pack2(l2, l3);
            } else if (EPI == 1) {
                *(float2*)(outf + (size_t)r0 * N + cc)       = make_float2(a[0], a[1]);
                *(float2*)(outf + (size_t)(r0 + 8) * N + cc) = make_float2(a[2], a[3]);
            } else {
                size_t o0 = (size_t)r0 * N + cc, o1 = (size_t)(r0 + 8) * N + cc;
                float2 f0 = *(const float2*)(biasF + o0);
                float2 f1 = *(const float2*)(biasF + o1);
                *(float2*)(outf + o0) = make_float2(0.5f * f0.x + 0.5f * a[0],
                                                    0.5f * f0.y + 0.5f * a[1]);
                *(float2*)(outf + o1) = make_float2(0.5f * f1.x + 0.5f * a[2],
                                                    0.5f * f1.y + 0.5f * a[3]);
            }
        }
    }
}

// ---------------- rowwise softmax: fp32 in, fp16 (hi only) out ----------------
__global__ __launch_bounds__(512)
void softmax_h(const float* __restrict__ S, __half* __restrict__ Ph, int cols)
{
    __shared__ float red[16];
    const int tid = threadIdx.x;
    const float4* p = (const float4*)(S + (size_t)blockIdx.x * cols);
    uint2* oh = (uint2*)(Ph + (size_t)blockIdx.x * cols);

    float4 v[4];
    float m = -1e30f;
#pragma unroll
    for (int i = 0; i < 4; ++i) {
        v[i] = p[tid + i * 512];
        m = fmaxf(m, fmaxf(fmaxf(v[i].x, v[i].y), fmaxf(v[i].z, v[i].w)));
    }
#pragma unroll
    for (int o = 16; o; o >>= 1) m = fmaxf(m, __shfl_xor_sync(0xffffffffu, m, o));
    if ((tid & 31) == 0) red[tid >> 5] = m;
    __syncthreads();
    if (tid < 32) {
        float t = (tid < 16) ? red[tid] : -1e30f;
#pragma unroll
        for (int o = 8; o; o >>= 1) t = fmaxf(t, __shfl_xor_sync(0xffffffffu, t, o));
        if (tid == 0) red[0] = t;
    }
    __syncthreads();
    m = red[0];
    __syncthreads();

    float sum = 0.f;
#pragma unroll
    for (int i = 0; i < 4; ++i) {
        v[i].x = __expf(v[i].x - m); v[i].y = __expf(v[i].y - m);
        v[i].z = __expf(v[i].z - m); v[i].w = __expf(v[i].w - m);
        sum += (v[i].x + v[i].y) + (v[i].z + v[i].w);
    }
#pragma unroll
    for (int o = 16; o; o >>= 1) sum += __shfl_xor_sync(0xffffffffu, sum, o);
    if ((tid & 31) == 0) red[tid >> 5] = sum;
    __syncthreads();
    if (tid < 32) {
        float t = (tid < 16) ? red[tid] : 0.f;
#pragma unroll
        for (int o = 8; o; o >>= 1) t += __shfl_xor_sync(0xffffffffu, t, o);
        if (tid == 0) red[0] = t;
    }
    __syncthreads();
    const float inv = 1.0f / red[0];

#pragma unroll
    for (int i = 0; i < 4; ++i) {
        oh[tid + i * 512] = make_uint2(
            pack2(__float2half_rn(v[i].x * inv), __float2half_rn(v[i].y * inv)),
            pack2(__float2half_rn(v[i].z * inv), __float2half_rn(v[i].w * inv)));
    }
}

// ---------------------------------------------------------------------------
extern "C" void kernel_launch(void* const* d_in, const int* in_sizes, int n_in,
                              void* d_out, int out_size)
{
    const float* features = (const float*)d_in[0];
    const float* memoryf  = (const float*)d_in[1];
    const float* Wq       = (const float*)d_in[2];
    const float* bq       = (const float*)d_in[3];
    const float* Wk       = (const float*)d_in[4];
    // bk cancels in softmax (per-row logit constant) -> unused
    float* out            = (float*)d_out;

    __half *fh, *fl, *mh, *ml, *t1h, *t1l, *qh, *ql, *mth, *ph;
    float *s, *cv;
    cudaGetSymbolAddress((void**)&fh, g_fh);   cudaGetSymbolAddress((void**)&fl, g_fl);
    cudaGetSymbolAddress((void**)&mh, g_mh);   cudaGetSymbolAddress((void**)&ml, g_ml);
    cudaGetSymbolAddress((void**)&t1h, g_t1h); cudaGetSymbolAddress((void**)&t1l, g_t1l);
    cudaGetSymbolAddress((void**)&qh, g_qh);   cudaGetSymbolAddress((void**)&ql, g_ql);
    cudaGetSymbolAddress((void**)&mth, g_mth); cudaGetSymbolAddress((void**)&ph, g_ph);
    cudaGetSymbolAddress((void**)&s, g_s);     cudaGetSymbolAddress((void**)&cv, g_c);

    const int SM3 = 2 * 4 * MAT_B;   // 81920 B : 3-pass, 2 stages
    const int SM1 = 4 * 2 * MAT_B;   // 81920 B : 1-pass, 4 stages
    cudaFuncSetAttribute((const void*)mma_gemm<0,3,2>, cudaFuncAttributeMaxDynamicSharedMemorySize, SM3);
    cudaFuncSetAttribute((const void*)mma_gemm<1,3,2>, cudaFuncAttributeMaxDynamicSharedMemorySize, SM3);
    cudaFuncSetAttribute((const void*)mma_gemm<2,1,4>, cudaFuncAttributeMaxDynamicSharedMemorySize, SM1);

    size_t n4 = (size_t)NR * HD / 4;
    unsigned half_blocks = (unsigned)((n4 + 255) / 256);

    // 1) split features + memory (one launch)
    split_fm_kernel<<<2 * half_blocks, 256>>>(features, memoryf, fh, fl, mh, ml, n4);

    // 2) T1 = Wk^T @ Wq (split) + c = bq @ Wk (fused)
    wprod_cvec_kernel<<<dim3(HD / 16, HD / 16), 256>>>(Wk, Wq, bq, t1h, t1l, cv);

    // 3) qw = f @ W1 + c  (3-pass, split fp16 out)
    mma_gemm<0,3,2><<<dim3(HD / 128, NR / 128), 128, SM3>>>(
        fh, fl, t1h, t1l, cv, nullptr, qh, ql, NR, HD, HD);

    // 4) S = qw @ mem^T  (3-pass, fp32 out)   <- ncu capture slot
    mma_gemm<1,3,2><<<dim3(MR / 128, NR / 128), 128, SM3>>>(
        qh, ql, mh, ml, nullptr, s, nullptr, nullptr, NR, MR, HD);

    // 5) memT (hi only) for the AV GEMM
    transpose_h<<<dim3(MR / 32, HD / 32), 256>>>(memoryf, mth);

    // 6) softmax -> fp16 P (hi only)
    softmax_h<<<NR, 512>>>(s, ph, MR);

    // 7) out = 0.5*features + 0.5*(P @ memT^T)  (1-pass, 4-stage)
    mma_gemm<2,1,4><<<dim3(HD / 128, NR / 128), 128, SM1>>>(
        ph, nullptr, mth, nullptr, features, out, nullptr, nullptr, NR, HD, MR);
}

// round 15
// speedup vs baseline: 1.1190x; 1.1190x over previous
#include <cuda_runtime.h>
#include <cuda_fp16.h>
#include <cstdint>
#include <cstddef>

#define NR 8192
#define MR 8192
#define HD 512

// ---------------- scratch (device globals: allowed) ----------------
__device__ __align__(128) __half g_fh[(size_t)NR * HD], g_fl[(size_t)NR * HD];
__device__ __align__(128) __half g_mh[(size_t)MR * HD], g_ml[(size_t)MR * HD];
__device__ __align__(128) __half g_t1h[HD * HD], g_t1l[HD * HD];
__device__ __align__(128) float  g_c[HD];
__device__ __align__(128) __half g_qh[(size_t)NR * HD], g_ql[(size_t)NR * HD];
__device__ __align__(128) __half g_mth[(size_t)HD * MR];
__device__ __align__(128) float  g_s[(size_t)NR * MR];
__device__ __align__(128) __half g_ph[(size_t)NR * MR];

// ---------------- helpers ----------------
__device__ __forceinline__ uint32_t smem_u32(const void* p) {
    uint32_t a;
    asm("{ .reg .u64 t; cvta.to.shared.u64 t, %1; cvt.u32.u64 %0, t; }" : "=r"(a) : "l"(p));
    return a;
}
__device__ __forceinline__ void cp16(uint32_t dst, const void* src) {
    asm volatile("cp.async.cg.shared.global [%0], [%1], 16;" :: "r"(dst), "l"(src));
}
__device__ __forceinline__ void ldsm4(uint32_t* r, uint32_t addr) {
    asm volatile("ldmatrix.sync.aligned.m8n8.x4.shared.b16 {%0,%1,%2,%3}, [%4];"
        : "=r"(r[0]), "=r"(r[1]), "=r"(r[2]), "=r"(r[3]) : "r"(addr));
}
__device__ __forceinline__ void mma16816(float* c, const uint32_t* a, const uint32_t* b) {
    asm volatile("mma.sync.aligned.m16n8k16.row.col.f32.f16.f16.f32 "
        "{%0,%1,%2,%3}, {%4,%5,%6,%7}, {%8,%9}, {%0,%1,%2,%3};"
        : "+f"(c[0]), "+f"(c[1]), "+f"(c[2]), "+f"(c[3])
        : "r"(a[0]), "r"(a[1]), "r"(a[2]), "r"(a[3]), "r"(b[0]), "r"(b[1]));
}
__device__ __forceinline__ void split1(float v, __half& h, __half& l) {
    h = __float2half_rn(v);
    l = __float2half_rn(v - __half2float(h));
}
__device__ __forceinline__ uint32_t pack2(__half a, __half b) {
    __half2 t = __halves2half2(a, b);
    return *(uint32_t*)&t;
}

// pitch: 32 halfs padded to 40 (80B) -> conflict-free ldmatrix
#define PITCH_B 80
#define MAT_B   (128 * PITCH_B)   // 10240 B per matrix tile

// ---------------- combined split: features AND memory in one launch ----------------
__global__ __launch_bounds__(256)
void split_fm_kernel(const float* __restrict__ f, const float* __restrict__ m,
                     __half* __restrict__ fh, __half* __restrict__ fl,
                     __half* __restrict__ mh, __half* __restrict__ ml, size_t n4)
{
    size_t half_blocks = gridDim.x >> 1;
    const float* s; __half *dh, *dl;
    size_t i;
    if (blockIdx.x < half_blocks) {
        s = f; dh = fh; dl = fl;
        i = (size_t)blockIdx.x * blockDim.x + threadIdx.x;
    } else {
        s = m; dh = mh; dl = ml;
        i = (size_t)(blockIdx.x - half_blocks) * blockDim.x + threadIdx.x;
    }
    if (i >= n4) return;
    float4 v = ((const float4*)s)[i];
    __half hx, lx, hy, ly, hz, lz, hw, lw;
    split1(v.x, hx, lx); split1(v.y, hy, ly);
    split1(v.z, hz, lz); split1(v.w, hw, lw);
    ((uint2*)dh)[i] = make_uint2(pack2(hx, hy), pack2(hz, hw));
    ((uint2*)dl)[i] = make_uint2(pack2(lx, ly), pack2(lz, lw));
}

// ---------------- T1 = Wk^T @ Wq (split-fp16) + c = bq @ Wk (fused) ----------------
__global__ __launch_bounds__(256)
void wprod_cvec_kernel(const float* __restrict__ Wk, const float* __restrict__ Wq,
                       const float* __restrict__ bq,
                       __half* __restrict__ Th, __half* __restrict__ Tl,
                       float* __restrict__ c)
{
    __shared__ float Ks[16][17], Qs[16][17];
    const int i0 = blockIdx.x * 16;
    const int j0 = blockIdx.y * 16;
    const int tx = threadIdx.x & 15;
    const int ty = threadIdx.x >> 4;
    float acc = 0.f;
    for (int t0 = 0; t0 < HD; t0 += 16) {
        Ks[ty][tx] = Wk[(t0 + ty) * HD + i0 + tx];
        Qs[ty][tx] = Wq[(t0 + ty) * HD + j0 + tx];
        __syncthreads();
#pragma unroll
        for (int t = 0; t < 16; ++t)
            acc = fmaf(Ks[t][ty], Qs[t][tx], acc);
        __syncthreads();
    }
    __half h, l; split1(acc, h, l);
    Th[(size_t)(i0 + ty) * HD + j0 + tx] = h;
    Tl[(size_t)(i0 + ty) * HD + j0 + tx] = l;

    if (blockIdx.y == 0) {
        __shared__ float cred[16][17];
        float a = 0.f;
#pragma unroll 4
        for (int t = tx * 32; t < tx * 32 + 32; ++t)
            a = fmaf(bq[t], Wk[t * HD + i0 + ty], a);
        cred[ty][tx] = a;
        __syncthreads();
        if (tx == 0) {
            float s2 = 0.f;
#pragma unroll
            for (int u = 0; u < 16; ++u) s2 += cred[ty][u];
            c[i0 + ty] = s2;
        }
    }
}

// ---------------- mem [MR][HD] fp32 -> memT [HD][MR] fp16 (hi only) ----------------
__global__ __launch_bounds__(256)
void transpose_h(const float* __restrict__ src, __half* __restrict__ dh)
{
    __shared__ float t[32][33];
    const int j0 = blockIdx.x * 32;
    const int h0 = blockIdx.y * 32;
    const int tx = threadIdx.x & 31;
    const int ty = threadIdx.x >> 5;
#pragma unroll
    for (int i = 0; i < 4; ++i)
        t[ty + i * 8][tx] = src[(size_t)(j0 + ty + i * 8) * HD + h0 + tx];
    __syncthreads();
#pragma unroll
    for (int i = 0; i < 4; ++i) {
        size_t o = (size_t)(h0 + ty + i * 8) * MR + j0 + tx;
        dh[o] = __float2half_rn(t[tx][ty + i * 8]);
    }
}

// ---------------------------------------------------------------------------
// NT GEMM via mma.sync, fp32 accumulate. FAT-WARP (R9 / best-known config):
// CTA 128x128, 128 threads, 4 warps 2x2, warp tile 64x64 (128 accum regs/thr).
// NPASS==3: D = Ah*Bh + Ah*Bl + Al*Bh   (stage mats: Ah,Bh,Bl,Al)
// NPASS==1: D = Ah*Bh                   (stage mats: Ah,Bh)
// Pass-major inner loop; K-chunk 32, NSTG-stage cp.async pipeline, 2 CTAs/SM.
// EPI: 0 = +bias[n], split fp16 out; 1 = fp32 out; 2 = 0.5*F + 0.5*acc (F=biasF)
// ---------------------------------------------------------------------------
template <int EPI, int NPASS, int NSTG>
__global__ __launch_bounds__(128, 2)
void mma_gemm(const __half* __restrict__ Ah, const __half* __restrict__ Al,
              const __half* __restrict__ Bh, const __half* __restrict__ Bl,
              const float* __restrict__ biasF,
              float* __restrict__ outf,
              __half* __restrict__ outh, __half* __restrict__ outl,
              int M, int N, int K)
{
    constexpr int NMAT = (NPASS == 3) ? 4 : 2;
    constexpr uint32_t STAGE = NMAT * MAT_B;

    extern __shared__ char smem[];
    const uint32_t sbase = smem_u32(smem);
    const int tid = threadIdx.x;
    const int wid = tid >> 5;
    const int lane = tid & 31;
    const int bm = blockIdx.y * 128;
    const int bn = blockIdx.x * 128;
    const int wm = (wid & 1) * 64;
    const int wn = (wid >> 1) * 64;

    const int NC = K >> 5;

    const int ldr = tid >> 2;
    const int ldc = (tid & 3) * 16;

    auto loadc = [&](int c) {
        const uint32_t sb = sbase + (uint32_t)(c % NSTG) * STAGE;
        const int k0 = c << 5;
        const __half* pa = Ah + (size_t)(bm + ldr) * K + k0 + ldc / 2;
        const __half* pb = Bh + (size_t)(bn + ldr) * K + k0 + ldc / 2;
#pragma unroll
        for (int i = 0; i < 4; ++i) {
            cp16(sb + (ldr + i * 32) * PITCH_B + ldc,         pa + (size_t)(i * 32) * K);
            cp16(sb + MAT_B + (ldr + i * 32) * PITCH_B + ldc, pb + (size_t)(i * 32) * K);
        }
        if (NPASS == 3) {
            const __half* pc = Bl + (size_t)(bn + ldr) * K + k0 + ldc / 2;
            const __half* pd = Al + (size_t)(bm + ldr) * K + k0 + ldc / 2;
#pragma unroll
            for (int i = 0; i < 4; ++i) {
                cp16(sb + 2 * MAT_B + (ldr + i * 32) * PITCH_B + ldc, pc + (size_t)(i * 32) * K);
                cp16(sb + 3 * MAT_B + (ldr + i * 32) * PITCH_B + ldc, pd + (size_t)(i * 32) * K);
            }
        }
    };

    float acc[4][8][4];
#pragma unroll
    for (int mg = 0; mg < 4; ++mg)
#pragma unroll
        for (int ng = 0; ng < 8; ++ng)
#pragma unroll
            for (int j = 0; j < 4; ++j) acc[mg][ng][j] = 0.f;

    const uint32_t aRow = (lane & 15);
    const uint32_t aChk = (lane >> 4);
    const uint32_t bRow = ((lane >> 4) & 1) * 8 + (lane & 7);
    const uint32_t bChk = (lane >> 3) & 1;

    auto compute = [&](int c) {
        const uint32_t st = sbase + (uint32_t)(c % NSTG) * STAGE;
#pragma unroll
        for (int ks = 0; ks < 2; ++ks) {
            uint32_t ah[4][4], al[4][4];
#pragma unroll
            for (int mg = 0; mg < 4; ++mg) {
                uint32_t off = (wm + mg * 16 + aRow) * PITCH_B + aChk * 16 + ks * 32;
                ldsm4(ah[mg], st + off);
                if (NPASS == 3) ldsm4(al[mg], st + 3 * MAT_B + off);
            }
#pragma unroll
            for (int ph = 0; ph < 2; ++ph) {
                uint32_t bh[2][4], bl[2][4];
#pragma unroll
                for (int p2 = 0; p2 < 2; ++p2) {
                    uint32_t off = (wn + (ph * 2 + p2) * 16 + bRow) * PITCH_B + bChk * 16 + ks * 32;
                    ldsm4(bh[p2], st + MAT_B + off);
                    if (NPASS == 3) ldsm4(bl[p2], st + 2 * MAT_B + off);
                }
                // pass 1: Ah * Bh
#pragma unroll
                for (int p2 = 0; p2 < 2; ++p2)
#pragma unroll
                    for (int mg = 0; mg < 4; ++mg) {
                        const int ng = 2 * (ph * 2 + p2);
                        mma16816(acc[mg][ng + 0], ah[mg], bh[p2] + 0);
                        mma16816(acc[mg][ng + 1], ah[mg], bh[p2] + 2);
                    }
                if (NPASS == 3) {
                    // pass 2: Ah * Bl
#pragma unroll
                    for (int p2 = 0; p2 < 2; ++p2)
#pragma unroll
                        for (int mg = 0; mg < 4; ++mg) {
                            const int ng = 2 * (ph * 2 + p2);
                            mma16816(acc[mg][ng + 0], ah[mg], bl[p2] + 0);
                            mma16816(acc[mg][ng + 1], ah[mg], bl[p2] + 2);
                        }
                    // pass 3: Al * Bh
#pragma unroll
                    for (int p2 = 0; p2 < 2; ++p2)
#pragma unroll
                        for (int mg = 0; mg < 4; ++mg) {
                            const int ng = 2 * (ph * 2 + p2);
                            mma16816(acc[mg][ng + 0], al[mg], bh[p2] + 0);
                            mma16816(acc[mg][ng + 1], al[mg], bh[p2] + 2);
                        }
                }
            }
        }
    };

    // pipeline: wait(chunk c) -> sync -> prefetch(c+NSTG-1) -> compute(c)
#pragma unroll 1
    for (int c = 0; c < NSTG - 1 && c < NC; ++c) {
        loadc(c);
        asm volatile("cp.async.commit_group;" ::: "memory");
    }
#pragma unroll 1
    for (int c = 0; c < NC; ++c) {
        if (NSTG >= 4 && c + 2 < NC)
            asm volatile("cp.async.wait_group 2;" ::: "memory");
        else if (NSTG >= 3 && c + 1 < NC)
            asm volatile("cp.async.wait_group 1;" ::: "memory");
        else
            asm volatile("cp.async.wait_group 0;" ::: "memory");
        __syncthreads();
        if (c + NSTG - 1 < NC) {
            loadc(c + NSTG - 1);
            asm volatile("cp.async.commit_group;" ::: "memory");
        }
        compute(c);
    }

    // ---------------- epilogue ----------------
#pragma unroll
    for (int mg = 0; mg < 4; ++mg) {
        const int r0 = bm + wm + mg * 16 + (lane >> 2);
#pragma unroll
        for (int ng = 0; ng < 8; ++ng) {
            const int cc = bn + wn + ng * 8 + (lane & 3) * 2;
            const float* a = acc[mg][ng];
            if (EPI == 0) {
                float b0 = biasF[cc], b1 = biasF[cc + 1];
                float v0 = a[0] + b0, v1 = a[1] + b1;
                float v2 = a[2] + b0, v3 = a[3] + b1;
                __half h0, l0, h1, l1, h2, l2, h3, l3;
                split1(v0, h0, l0); split1(v1, h1, l1);
                split1(v2, h2, l2); split1(v3, h3, l3);
                *(uint32_t*)(outh + (size_t)r0 * N + cc)       = pack2(h0, h1);
                *(uint32_t*)(outl + (size_t)r0 * N + cc)       = pack2(l0, l1);
                *(uint32_t*)(outh + (size_t)(r0 + 8) * N + cc) = pack2(h2, h3);
                *(uint32_t*)(outl + (size_t)(r0 + 8) * N + cc) = pack2(l2, l3);
            } else if (EPI == 1) {
                *(float2*)(outf + (size_t)r0 * N + cc)       = make_float2(a[0], a[1]);
                *(float2*)(outf + (size_t)(r0 + 8) * N + cc) = make_float2(a[2], a[3]);
            } else {
                size_t o0 = (size_t)r0 * N + cc, o1 = (size_t)(r0 + 8) * N + cc;
                float2 f0 = *(const float2*)(biasF + o0);
                float2 f1 = *(const float2*)(biasF + o1);
                *(float2*)(outf + o0) = make_float2(0.5f * f0.x + 0.5f * a[0],
                                                    0.5f * f0.y + 0.5f * a[1]);
                *(float2*)(outf + o1) = make_float2(0.5f * f1.x + 0.5f * a[2],
                                                    0.5f * f1.y + 0.5f * a[3]);
            }
        }
    }
}

// ---------------- rowwise softmax: fp32 in, fp16 (hi only) out ----------------
__global__ __launch_bounds__(512)
void softmax_h(const float* __restrict__ S, __half* __restrict__ Ph, int cols)
{
    __shared__ float red[16];
    const int tid = threadIdx.x;
    const float4* p = (const float4*)(S + (size_t)blockIdx.x * cols);
    uint2* oh = (uint2*)(Ph + (size_t)blockIdx.x * cols);

    float4 v[4];
    float m = -1e30f;
#pragma unroll
    for (int i = 0; i < 4; ++i) {
        v[i] = p[tid + i * 512];
        m = fmaxf(m, fmaxf(fmaxf(v[i].x, v[i].y), fmaxf(v[i].z, v[i].w)));
    }
#pragma unroll
    for (int o = 16; o; o >>= 1) m = fmaxf(m, __shfl_xor_sync(0xffffffffu, m, o));
    if ((tid & 31) == 0) red[tid >> 5] = m;
    __syncthreads();
    if (tid < 32) {
        float t = (tid < 16) ? red[tid] : -1e30f;
#pragma unroll
        for (int o = 8; o; o >>= 1) t = fmaxf(t, __shfl_xor_sync(0xffffffffu, t, o));
        if (tid == 0) red[0] = t;
    }
    __syncthreads();
    m = red[0];
    __syncthreads();

    float sum = 0.f;
#pragma unroll
    for (int i = 0; i < 4; ++i) {
        v[i].x = __expf(v[i].x - m); v[i].y = __expf(v[i].y - m);
        v[i].z = __expf(v[i].z - m); v[i].w = __expf(v[i].w - m);
        sum += (v[i].x + v[i].y) + (v[i].z + v[i].w);
    }
#pragma unroll
    for (int o = 16; o; o >>= 1) sum += __shfl_xor_sync(0xffffffffu, sum, o);
    if ((tid & 31) == 0) red[tid >> 5] = sum;
    __syncthreads();
    if (tid < 32) {
        float t = (tid < 16) ? red[tid] : 0.f;
#pragma unroll
        for (int o = 8; o; o >>= 1) t += __shfl_xor_sync(0xffffffffu, t, o);
        if (tid == 0) red[0] = t;
    }
    __syncthreads();
    const float inv = 1.0f / red[0];

#pragma unroll
    for (int i = 0; i < 4; ++i) {
        oh[tid + i * 512] = make_uint2(
            pack2(__float2half_rn(v[i].x * inv), __float2half_rn(v[i].y * inv)),
            pack2(__float2half_rn(v[i].z * inv), __float2half_rn(v[i].w * inv)));
    }
}

// ---------------------------------------------------------------------------
extern "C" void kernel_launch(void* const* d_in, const int* in_sizes, int n_in,
                              void* d_out, int out_size)
{
    const float* features = (const float*)d_in[0];
    const float* memoryf  = (const float*)d_in[1];
    const float* Wq       = (const float*)d_in[2];
    const float* bq       = (const float*)d_in[3];
    const float* Wk       = (const float*)d_in[4];
    // bk cancels in softmax (per-row logit constant) -> unused
    float* out            = (float*)d_out;

    __half *fh, *fl, *mh, *ml, *t1h, *t1l, *qh, *ql, *mth, *ph;
    float *s, *cv;
    cudaGetSymbolAddress((void**)&fh, g_fh);   cudaGetSymbolAddress((void**)&fl, g_fl);
    cudaGetSymbolAddress((void**)&mh, g_mh);   cudaGetSymbolAddress((void**)&ml, g_ml);
    cudaGetSymbolAddress((void**)&t1h, g_t1h); cudaGetSymbolAddress((void**)&t1l, g_t1l);
    cudaGetSymbolAddress((void**)&qh, g_qh);   cudaGetSymbolAddress((void**)&ql, g_ql);
    cudaGetSymbolAddress((void**)&mth, g_mth); cudaGetSymbolAddress((void**)&ph, g_ph);
    cudaGetSymbolAddress((void**)&s, g_s);     cudaGetSymbolAddress((void**)&cv, g_c);

    const int SM3 = 2 * 4 * MAT_B;   // 81920 B : 3-pass, 2 stages
    const int SM1 = 4 * 2 * MAT_B;   // 81920 B : 1-pass, 4 stages
    cudaFuncSetAttribute((const void*)mma_gemm<0,3,2>, cudaFuncAttributeMaxDynamicSharedMemorySize, SM3);
    cudaFuncSetAttribute((const void*)mma_gemm<1,3,2>, cudaFuncAttributeMaxDynamicSharedMemorySize, SM3);
    cudaFuncSetAttribute((const void*)mma_gemm<2,1,4>, cudaFuncAttributeMaxDynamicSharedMemorySize, SM1);

    size_t n4 = (size_t)NR * HD / 4;
    unsigned half_blocks = (unsigned)((n4 + 255) / 256);

    // 1) split features + memory (one launch)
    split_fm_kernel<<<2 * half_blocks, 256>>>(features, memoryf, fh, fl, mh, ml, n4);

    // 2) T1 = Wk^T @ Wq (split) + c = bq @ Wk (fused)
    wprod_cvec_kernel<<<dim3(HD / 16, HD / 16), 256>>>(Wk, Wq, bq, t1h, t1l, cv);

    // 3) qw = f @ W1 + c  (3-pass, split fp16 out)
    mma_gemm<0,3,2><<<dim3(HD / 128, NR / 128), 128, SM3>>>(
        fh, fl, t1h, t1l, cv, nullptr, qh, ql, NR, HD, HD);

    // 4) S = qw @ mem^T  (3-pass, fp32 out)   <- ncu capture slot
    mma_gemm<1,3,2><<<dim3(MR / 128, NR / 128), 128, SM3>>>(
        qh, ql, mh, ml, nullptr, s, nullptr, nullptr, NR, MR, HD);

    // 5) memT (hi only) for the AV GEMM
    transpose_h<<<dim3(MR / 32, HD / 32), 256>>>(memoryf, mth);

    // 6) softmax -> fp16 P (hi only)
    softmax_h<<<NR, 512>>>(s, ph, MR);

    // 7) out = 0.5*features + 0.5*(P @ memT^T)  (1-pass, 4-stage)
    mma_gemm<2,1,4><<<dim3(HD / 128, NR / 128), 128, SM1>>>(
        ph, nullptr, mth, nullptr, features, out, nullptr, nullptr, NR, HD, MR);
}

// round 16
// speedup vs baseline: 1.2592x; 1.1253x over previous
#include <cuda_runtime.h>
#include <cuda_fp16.h>
#include <cstdint>
#include <cstddef>

#define NR 8192
#define MR 8192
#define HD 512

// ---------------- scratch (device globals: allowed) ----------------
__device__ __align__(128) __half g_fh[(size_t)NR * HD], g_fl[(size_t)NR * HD];
__device__ __align__(128) __half g_mh[(size_t)MR * HD], g_ml[(size_t)MR * HD];
__device__ __align__(128) __half g_t1h[HD * HD], g_t1l[HD * HD];
__device__ __align__(128) float  g_c[HD];
__device__ __align__(128) __half g_qh[(size_t)NR * HD], g_ql[(size_t)NR * HD];
__device__ __align__(128) __half g_mth[(size_t)HD * MR];
__device__ __align__(128) float  g_s[(size_t)NR * MR];
__device__ __align__(128) __half g_ph[(size_t)NR * MR];

// ---------------- helpers ----------------
__device__ __forceinline__ uint32_t smem_u32(const void* p) {
    uint32_t a;
    asm("{ .reg .u64 t; cvta.to.shared.u64 t, %1; cvt.u32.u64 %0, t; }" : "=r"(a) : "l"(p));
    return a;
}
__device__ __forceinline__ void cp16(uint32_t dst, const void* src) {
    asm volatile("cp.async.cg.shared.global [%0], [%1], 16;" :: "r"(dst), "l"(src));
}
__device__ __forceinline__ void ldsm4(uint32_t* r, uint32_t addr) {
    asm volatile("ldmatrix.sync.aligned.m8n8.x4.shared.b16 {%0,%1,%2,%3}, [%4];"
        : "=r"(r[0]), "=r"(r[1]), "=r"(r[2]), "=r"(r[3]) : "r"(addr));
}
__device__ __forceinline__ void mma16816(float* c, const uint32_t* a, const uint32_t* b) {
    asm volatile("mma.sync.aligned.m16n8k16.row.col.f32.f16.f16.f32 "
        "{%0,%1,%2,%3}, {%4,%5,%6,%7}, {%8,%9}, {%0,%1,%2,%3};"
        : "+f"(c[0]), "+f"(c[1]), "+f"(c[2]), "+f"(c[3])
        : "r"(a[0]), "r"(a[1]), "r"(a[2]), "r"(a[3]), "r"(b[0]), "r"(b[1]));
}
__device__ __forceinline__ void split1(float v, __half& h, __half& l) {
    h = __float2half_rn(v);
    l = __float2half_rn(v - __half2float(h));
}
__device__ __forceinline__ uint32_t pack2(__half a, __half b) {
    __half2 t = __halves2half2(a, b);
    return *(uint32_t*)&t;
}

// XOR-swizzled tile: 128 rows x 64B (32 halfs), NO padding.
// phys addr(row, chunk16) = row*64 + (chunk ^ ((row>>1)&3))*16
// -> conflict-free for cp.async 16B writes and ldmatrix.x4 reads.
#define MAT_SW  8192   // 128 * 64 bytes per matrix tile

// ---------------- combined split: features AND memory in one launch ----------------
__global__ __launch_bounds__(256)
void split_fm_kernel(const float* __restrict__ f, const float* __restrict__ m,
                     __half* __restrict__ fh, __half* __restrict__ fl,
                     __half* __restrict__ mh, __half* __restrict__ ml, size_t n4)
{
    size_t half_blocks = gridDim.x >> 1;
    const float* s; __half *dh, *dl;
    size_t i;
    if (blockIdx.x < half_blocks) {
        s = f; dh = fh; dl = fl;
        i = (size_t)blockIdx.x * blockDim.x + threadIdx.x;
    } else {
        s = m; dh = mh; dl = ml;
        i = (size_t)(blockIdx.x - half_blocks) * blockDim.x + threadIdx.x;
    }
    if (i >= n4) return;
    float4 v = ((const float4*)s)[i];
    __half hx, lx, hy, ly, hz, lz, hw, lw;
    split1(v.x, hx, lx); split1(v.y, hy, ly);
    split1(v.z, hz, lz); split1(v.w, hw, lw);
    ((uint2*)dh)[i] = make_uint2(pack2(hx, hy), pack2(hz, hw));
    ((uint2*)dl)[i] = make_uint2(pack2(lx, ly), pack2(lz, lw));
}

// ---------------- T1 = Wk^T @ Wq (split-fp16) + c = bq @ Wk (fused) ----------------
__global__ __launch_bounds__(256)
void wprod_cvec_kernel(const float* __restrict__ Wk, const float* __restrict__ Wq,
                       const float* __restrict__ bq,
                       __half* __restrict__ Th, __half* __restrict__ Tl,
                       float* __restrict__ c)
{
    __shared__ float Ks[16][17], Qs[16][17];
    const int i0 = blockIdx.x * 16;
    const int j0 = blockIdx.y * 16;
    const int tx = threadIdx.x & 15;
    const int ty = threadIdx.x >> 4;
    float acc = 0.f;
    for (int t0 = 0; t0 < HD; t0 += 16) {
        Ks[ty][tx] = Wk[(t0 + ty) * HD + i0 + tx];
        Qs[ty][tx] = Wq[(t0 + ty) * HD + j0 + tx];
        __syncthreads();
#pragma unroll
        for (int t = 0; t < 16; ++t)
            acc = fmaf(Ks[t][ty], Qs[t][tx], acc);
        __syncthreads();
    }
    __half h, l; split1(acc, h, l);
    Th[(size_t)(i0 + ty) * HD + j0 + tx] = h;
    Tl[(size_t)(i0 + ty) * HD + j0 + tx] = l;

    if (blockIdx.y == 0) {
        __shared__ float cred[16][17];
        float a = 0.f;
#pragma unroll 4
        for (int t = tx * 32; t < tx * 32 + 32; ++t)
            a = fmaf(bq[t], Wk[t * HD + i0 + ty], a);
        cred[ty][tx] = a;
        __syncthreads();
        if (tx == 0) {
            float s2 = 0.f;
#pragma unroll
            for (int u = 0; u < 16; ++u) s2 += cred[ty][u];
            c[i0 + ty] = s2;
        }
    }
}

// ---------------- mem [MR][HD] fp32 -> memT [HD][MR] fp16 (hi only) ----------------
__global__ __launch_bounds__(256)
void transpose_h(const float* __restrict__ src, __half* __restrict__ dh)
{
    __shared__ float t[32][33];
    const int j0 = blockIdx.x * 32;
    const int h0 = blockIdx.y * 32;
    const int tx = threadIdx.x & 31;
    const int ty = threadIdx.x >> 5;
#pragma unroll
    for (int i = 0; i < 4; ++i)
        t[ty + i * 8][tx] = src[(size_t)(j0 + ty + i * 8) * HD + h0 + tx];
    __syncthreads();
#pragma unroll
    for (int i = 0; i < 4; ++i) {
        size_t o = (size_t)(h0 + ty + i * 8) * MR + j0 + tx;
        dh[o] = __float2half_rn(t[tx][ty + i * 8]);
    }
}

// ---------------------------------------------------------------------------
// NT GEMM via mma.sync, fp32 accumulate. FAT-WARP 128x128 CTA, 4 warps 2x2,
// warp tile 64x64. XOR-swizzled 64B-pitch smem tiles (no padding):
//   stage = NMAT*8KB -> NSTG=3 (3-pass) / NSTG=6 (1-pass) at 2 CTAs/SM.
// NPASS==3: D = Ah*Bh + Ah*Bl + Al*Bh   (stage: Ah,Bh,Bl,Al)
// NPASS==1: D = Ah*Bh                   (stage: Ah,Bh)
// EPI: 0 = +bias[n], split fp16 out; 1 = fp32 out; 2 = 0.5*F + 0.5*acc (F=biasF)
// ---------------------------------------------------------------------------
template <int EPI, int NPASS, int NSTG>
__global__ __launch_bounds__(128, 2)
void mma_gemm(const __half* __restrict__ Ah, const __half* __restrict__ Al,
              const __half* __restrict__ Bh, const __half* __restrict__ Bl,
              const float* __restrict__ biasF,
              float* __restrict__ outf,
              __half* __restrict__ outh, __half* __restrict__ outl,
              int M, int N, int K)
{
    constexpr int NMAT = (NPASS == 3) ? 4 : 2;
    constexpr uint32_t STAGE = NMAT * MAT_SW;

    extern __shared__ char smem[];
    const uint32_t sbase = smem_u32(smem);
    const int tid = threadIdx.x;
    const int wid = tid >> 5;
    const int lane = tid & 31;
    const int bm = blockIdx.y * 128;
    const int bn = blockIdx.x * 128;
    const int wm = (wid & 1) * 64;
    const int wn = (wid >> 1) * 64;

    const int NC = K >> 5;

    // global->smem mapping: thread = (row ldr, 16B chunk ldc4); xor constant/thread
    const int ldr = tid >> 2;                 // 0..31 (x4 row groups of 32)
    const int ldc4 = tid & 3;                 // logical 16B chunk in 64B row
    const uint32_t wXor = (uint32_t)((ldr >> 1) & 3);   // invariant under +32 rows
    const uint32_t sWoff = (uint32_t)(ldr * 64 + ((ldc4 ^ wXor) << 4));

    auto loadc = [&](int c) {
        const uint32_t sb = sbase + (uint32_t)(c % NSTG) * STAGE;
        const int k0 = (c << 5) + ldc4 * 8;   // logical K offset (halfs)
        const __half* pa = Ah + (size_t)(bm + ldr) * K + k0;
        const __half* pb = Bh + (size_t)(bn + ldr) * K + k0;
#pragma unroll
        for (int i = 0; i < 4; ++i) {
            cp16(sb + sWoff + i * (32 * 64),          pa + (size_t)(i * 32) * K);
            cp16(sb + MAT_SW + sWoff + i * (32 * 64), pb + (size_t)(i * 32) * K);
        }
        if (NPASS == 3) {
            const __half* pc = Bl + (size_t)(bn + ldr) * K + k0;
            const __half* pd = Al + (size_t)(bm + ldr) * K + k0;
#pragma unroll
            for (int i = 0; i < 4; ++i) {
                cp16(sb + 2 * MAT_SW + sWoff + i * (32 * 64), pc + (size_t)(i * 32) * K);
                cp16(sb + 3 * MAT_SW + sWoff + i * (32 * 64), pd + (size_t)(i * 32) * K);
            }
        }
    };

    float acc[4][8][4];
#pragma unroll
    for (int mg = 0; mg < 4; ++mg)
#pragma unroll
        for (int ng = 0; ng < 8; ++ng)
#pragma unroll
            for (int j = 0; j < 4; ++j) acc[mg][ng][j] = 0.f;

    // ldmatrix lane mapping + per-thread xor constants
    const uint32_t aRow = (lane & 15);
    const uint32_t aChk = (lane >> 4);                       // 0/1
    const uint32_t bRow = ((lane >> 4) & 1) * 8 + (lane & 7);
    const uint32_t bChk = (lane >> 3) & 1;
    const uint32_t aXor = (((wm + aRow) >> 1) & 3);          // invariant under +16 rows
    const uint32_t bXor = (((wn + bRow) >> 1) & 3);

    auto compute = [&](int c) {
        const uint32_t st = sbase + (uint32_t)(c % NSTG) * STAGE;
#pragma unroll
        for (int ks = 0; ks < 2; ++ks) {
            const uint32_t aCh = ((aChk | (ks << 1)) ^ aXor) << 4;
            const uint32_t bCh = ((bChk | (ks << 1)) ^ bXor) << 4;
            uint32_t ah[4][4], al[4][4];
#pragma unroll
            for (int mg = 0; mg < 4; ++mg) {
                uint32_t off = (wm + mg * 16 + aRow) * 64 + aCh;
                ldsm4(ah[mg], st + off);
                if (NPASS == 3) ldsm4(al[mg], st + 3 * MAT_SW + off);
            }
#pragma unroll
            for (int ph = 0; ph < 2; ++ph) {
                uint32_t bh[2][4], bl[2][4];
#pragma unroll
                for (int p2 = 0; p2 < 2; ++p2) {
                    uint32_t off = (wn + (ph * 2 + p2) * 16 + bRow) * 64 + bCh;
                    ldsm4(bh[p2], st + MAT_SW + off);
                    if (NPASS == 3) ldsm4(bl[p2], st + 2 * MAT_SW + off);
                }
                // pass 1: Ah * Bh
#pragma unroll
                for (int p2 = 0; p2 < 2; ++p2)
#pragma unroll
                    for (int mg = 0; mg < 4; ++mg) {
                        const int ng = 2 * (ph * 2 + p2);
                        mma16816(acc[mg][ng + 0], ah[mg], bh[p2] + 0);
                        mma16816(acc[mg][ng + 1], ah[mg], bh[p2] + 2);
                    }
                if (NPASS == 3) {
                    // pass 2: Ah * Bl
#pragma unroll
                    for (int p2 = 0; p2 < 2; ++p2)
#pragma unroll
                        for (int mg = 0; mg < 4; ++mg) {
                            const int ng = 2 * (ph * 2 + p2);
                            mma16816(acc[mg][ng + 0], ah[mg], bl[p2] + 0);
                            mma16816(acc[mg][ng + 1], ah[mg], bl[p2] + 2);
                        }
                    // pass 3: Al * Bh
#pragma unroll
                    for (int p2 = 0; p2 < 2; ++p2)
#pragma unroll
                        for (int mg = 0; mg < 4; ++mg) {
                            const int ng = 2 * (ph * 2 + p2);
                            mma16816(acc[mg][ng + 0], al[mg], bh[p2] + 0);
                            mma16816(acc[mg][ng + 1], al[mg], bh[p2] + 2);
                        }
                }
            }
        }
    };

    // pipeline: wait(chunk c) -> sync -> prefetch(c+NSTG-1) -> compute(c)
#pragma unroll 1
    for (int c = 0; c < NSTG - 1 && c < NC; ++c) {
        loadc(c);
        asm volatile("cp.async.commit_group;" ::: "memory");
    }
#pragma unroll 1
    for (int c = 0; c < NC; ++c) {
        if (c <= NC - NSTG + 1 && NSTG >= 3)
            asm volatile("cp.async.wait_group %0;" :: "n"(NSTG - 2) : "memory");
        else
            asm volatile("cp.async.wait_group 0;" ::: "memory");
        __syncthreads();
        if (c + NSTG - 1 < NC) {
            loadc(c + NSTG - 1);
            asm volatile("cp.async.commit_group;" ::: "memory");
        }
        compute(c);
    }

    // ---------------- epilogue ----------------
#pragma unroll
    for (int mg = 0; mg < 4; ++mg) {
        const int r0 = bm + wm + mg * 16 + (lane >> 2);
#pragma unroll
        for (int ng = 0; ng < 8; ++ng) {
            const int cc = bn + wn + ng * 8 + (lane & 3) * 2;
            const float* a = acc[mg][ng];
            if (EPI == 0) {
                float b0 = biasF[cc], b1 = biasF[cc + 1];
                float v0 = a[0] + b0, v1 = a[1] + b1;
                float v2 = a[2] + b0, v3 = a[3] + b1;
                __half h0, l0, h1, l1, h2, l2, h3, l3;
                split1(v0, h0, l0); split1(v1, h1, l1);
                split1(v2, h2, l2); split1(v3, h3, l3);
                *(uint32_t*)(outh + (size_t)r0 * N + cc)       = pack2(h0, h1);
                *(uint32_t*)(outl + (size_t)r0 * N + cc)       = pack2(l0, l1);
                *(uint32_t*)(outh + (size_t)(r0 + 8) * N + cc) = pack2(h2, h3);
                *(uint32_t*)(outl + (size_t)(r0 + 8) * N + cc) = pack2(l2, l3);
            } else if (EPI == 1) {
                *(float2*)(outf + (size_t)r0 * N + cc)       = make_float2(a[0], a[1]);
                *(float2*)(outf + (size_t)(r0 + 8) * N + cc) = make_float2(a[2], a[3]);
            } else {
                size_t o0 = (size_t)r0 * N + cc, o1 = (size_t)(r0 + 8) * N + cc;
                float2 f0 = *(const float2*)(biasF + o0);
                float2 f1 = *(const float2*)(biasF + o1);
                *(float2*)(outf + o0) = make_float2(0.5f * f0.x + 0.5f * a[0],
                                                    0.5f * f0.y + 0.5f * a[1]);
                *(float2*)(outf + o1) = make_float2(0.5f * f1.x + 0.5f * a[2],
                                                    0.5f * f1.y + 0.5f * a[3]);
            }
        }
    }
}

// ---------------- rowwise softmax: fp32 in, fp16 (hi only) out ----------------
__global__ __launch_bounds__(512)
void softmax_h(const float* __restrict__ S, __half* __restrict__ Ph, int cols)
{
    __shared__ float red[16];
    const int tid = threadIdx.x;
    const float4* p = (const float4*)(S + (size_t)blockIdx.x * cols);
    uint2* oh = (uint2*)(Ph + (size_t)blockIdx.x * cols);

    float4 v[4];
    float m = -1e30f;
#pragma unroll
    for (int i = 0; i < 4; ++i) {
        v[i] = p[tid + i * 512];
        m = fmaxf(m, fmaxf(fmaxf(v[i].x, v[i].y), fmaxf(v[i].z, v[i].w)));
    }
#pragma unroll
    for (int o = 16; o; o >>= 1) m = fmaxf(m, __shfl_xor_sync(0xffffffffu, m, o));
    if ((tid & 31) == 0) red[tid >> 5] = m;
    __syncthreads();
    if (tid < 32) {
        float t = (tid < 16) ? red[tid] : -1e30f;
#pragma unroll
        for (int o = 8; o; o >>= 1) t = fmaxf(t, __shfl_xor_sync(0xffffffffu, t, o));
        if (tid == 0) red[0] = t;
    }
    __syncthreads();
    m = red[0];
    __syncthreads();

    float sum = 0.f;
#pragma unroll
    for (int i = 0; i < 4; ++i) {
        v[i].x = __expf(v[i].x - m); v[i].y = __expf(v[i].y - m);
        v[i].z = __expf(v[i].z - m); v[i].w = __expf(v[i].w - m);
        sum += (v[i].x + v[i].y) + (v[i].z + v[i].w);
    }
#pragma unroll
    for (int o = 16; o; o >>= 1) sum += __shfl_xor_sync(0xffffffffu, sum, o);
    if ((tid & 31) == 0) red[tid >> 5] = sum;
    __syncthreads();
    if (tid < 32) {
        float t = (tid < 16) ? red[tid] : 0.f;
#pragma unroll
        for (int o = 8; o; o >>= 1) t += __shfl_xor_sync(0xffffffffu, t, o);
        if (tid == 0) red[0] = t;
    }
    __syncthreads();
    const float inv = 1.0f / red[0];

#pragma unroll
    for (int i = 0; i < 4; ++i) {
        oh[tid + i * 512] = make_uint2(
            pack2(__float2half_rn(v[i].x * inv), __float2half_rn(v[i].y * inv)),
            pack2(__float2half_rn(v[i].z * inv), __float2half_rn(v[i].w * inv)));
    }
}

// ---------------------------------------------------------------------------
extern "C" void kernel_launch(void* const* d_in, const int* in_sizes, int n_in,
                              void* d_out, int out_size)
{
    const float* features = (const float*)d_in[0];
    const float* memoryf  = (const float*)d_in[1];
    const float* Wq       = (const float*)d_in[2];
    const float* bq       = (const float*)d_in[3];
    const float* Wk       = (const float*)d_in[4];
    // bk cancels in softmax (per-row logit constant) -> unused
    float* out            = (float*)d_out;

    __half *fh, *fl, *mh, *ml, *t1h, *t1l, *qh, *ql, *mth, *ph;
    float *s, *cv;
    cudaGetSymbolAddress((void**)&fh, g_fh);   cudaGetSymbolAddress((void**)&fl, g_fl);
    cudaGetSymbolAddress((void**)&mh, g_mh);   cudaGetSymbolAddress((void**)&ml, g_ml);
    cudaGetSymbolAddress((void**)&t1h, g_t1h); cudaGetSymbolAddress((void**)&t1l, g_t1l);
    cudaGetSymbolAddress((void**)&qh, g_qh);   cudaGetSymbolAddress((void**)&ql, g_ql);
    cudaGetSymbolAddress((void**)&mth, g_mth); cudaGetSymbolAddress((void**)&ph, g_ph);
    cudaGetSymbolAddress((void**)&s, g_s);     cudaGetSymbolAddress((void**)&cv, g_c);

    const int SM3 = 3 * 4 * MAT_SW;   // 98304 B : 3-pass, 3 stages
    const int SM1 = 6 * 2 * MAT_SW;   // 98304 B : 1-pass, 6 stages
    cudaFuncSetAttribute((const void*)mma_gemm<0,3,3>, cudaFuncAttributeMaxDynamicSharedMemorySize, SM3);
    cudaFuncSetAttribute((const void*)mma_gemm<1,3,3>, cudaFuncAttributeMaxDynamicSharedMemorySize, SM3);
    cudaFuncSetAttribute((const void*)mma_gemm<2,1,6>, cudaFuncAttributeMaxDynamicSharedMemorySize, SM1);

    size_t n4 = (size_t)NR * HD / 4;
    unsigned half_blocks = (unsigned)((n4 + 255) / 256);

    // 1) split features + memory (one launch)
    split_fm_kernel<<<2 * half_blocks, 256>>>(features, memoryf, fh, fl, mh, ml, n4);

    // 2) T1 = Wk^T @ Wq (split) + c = bq @ Wk (fused)
    wprod_cvec_kernel<<<dim3(HD / 16, HD / 16), 256>>>(Wk, Wq, bq, t1h, t1l, cv);

    // 3) qw = f @ W1 + c  (3-pass, split fp16 out)
    mma_gemm<0,3,3><<<dim3(HD / 128, NR / 128), 128, SM3>>>(
        fh, fl, t1h, t1l, cv, nullptr, qh, ql, NR, HD, HD);

    // 4) S = qw @ mem^T  (3-pass, fp32 out)   <- ncu capture slot
    mma_gemm<1,3,3><<<dim3(MR / 128, NR / 128), 128, SM3>>>(
        qh, ql, mh, ml, nullptr, s, nullptr, nullptr, NR, MR, HD);

    // 5) memT (hi only) for the AV GEMM
    transpose_h<<<dim3(MR / 32, HD / 32), 256>>>(memoryf, mth);

    // 6) softmax -> fp16 P (hi only)
    softmax_h<<<NR, 512>>>(s, ph, MR);

    // 7) out = 0.5*features + 0.5*(P @ memT^T)  (1-pass, 6-stage)
    mma_gemm<2,1,6><<<dim3(HD / 128, NR / 128), 128, SM1>>>(
        ph, nullptr, mth, nullptr, features, out, nullptr, nullptr, NR, HD, MR);
}